// round 1
// baseline (speedup 1.0000x reference)
#include <cuda_runtime.h>
#include <math.h>

#define BATCH 2
#define CCH   32
#define HH    512
#define WWID  512
#define HS    256
#define WS    256
#define NBC   (BATCH*CCH)          // 64
#define CHW1  (CCH*HS*WS)          // 2097152, stride between p-slices of indices

#define TWOPI 6.28318530717958647692f

// ---------------- scratch (no allocations allowed) ----------------
__device__ float  g_part[BATCH*64*512];
__device__ float  g_F4r[BATCH*4];
__device__ float  g_F4i[BATCH*4];
__device__ float  g_LUTr[NBC*256];
__device__ float  g_LUTi[NBC*256];
__device__ unsigned char g_codemap[HS*WS];
__device__ float2 g_tmp[(size_t)NBC*HS*WS];   // 33.5 MB row-FFT intermediate (transposed)

// ---------------- K1: partial column sums of x[b,0] ----------------
__global__ void k_colsum(const float* __restrict__ x) {
    int rb = blockIdx.x;           // 0..63 (8 rows each)
    int b  = blockIdx.y;           // 0..1
    int w  = threadIdx.x;          // 0..511
    const float* base = x + (size_t)b*CCH*HH*WWID + (size_t)rb*8*WWID + w;
    float s = 0.f;
    #pragma unroll
    for (int r = 0; r < 8; r++) s += base[(size_t)r*WWID];
    g_part[(b*64 + rb)*512 + w] = s;
}

// ---------------- K2: F4[b,k] = sum_w colsum[w] * e^{-2pi i k w / 512}, k=0..3 ----------------
__global__ void k_f4() {
    int b = blockIdx.x;
    int w = threadIdx.x;           // 0..511
    float cs = 0.f;
    for (int rb = 0; rb < 64; rb++) cs += g_part[(b*64 + rb)*512 + w];
    __shared__ float red[512];
    for (int k = 0; k < 4; k++) {
        float ang = -TWOPI * (float)(k * w) / 512.0f;
        float sn, cn; sincosf(ang, &sn, &cn);
        red[w] = cs * cn; __syncthreads();
        for (int off = 256; off > 0; off >>= 1) { if (w < off) red[w] += red[w + off]; __syncthreads(); }
        if (w == 0) g_F4r[b*4 + k] = red[0];
        __syncthreads();
        red[w] = cs * sn; __syncthreads();
        for (int off = 256; off > 0; off >>= 1) { if (w < off) red[w] += red[w + off]; __syncthreads(); }
        if (w == 0) g_F4i[b*4 + k] = red[0];
        __syncthreads();
    }
}

// ---------------- K3: per-(b,c) 256-entry output LUT over permutation codes ----------------
__global__ void k_lut(const float* __restrict__ w1r, const float* __restrict__ b1r,
                      const float* __restrict__ w2r, const float* __restrict__ b2r,
                      const float* __restrict__ w1i, const float* __restrict__ b1i,
                      const float* __restrict__ w2i, const float* __restrict__ b2i) {
    int bc = blockIdx.x;           // 0..63
    int b  = bc >> 5;
    int c  = bc & 31;
    int code = threadIdx.x;        // 0..255
    float Fr[4], Fi[4];
    #pragma unroll
    for (int k = 0; k < 4; k++) { Fr[k] = g_F4r[b*4 + k]; Fi[k] = g_F4i[b*4 + k]; }
    int o  = c & 3;
    int gb = c >> 2;
    float vr[4], vi[4], wr[4], wi[4];
    #pragma unroll
    for (int p = 0; p < 4; p++) {
        int k = (code >> (2*p)) & 3;      // sigma(p)
        float vrp = Fr[k], vip = Fi[k];
        vr[p] = vrp; vi[p] = vip;
        int g = p*8 + gb;                  // group = (p*32+c)/4
        float accr = b2r[g*4 + o];
        float acci = b2i[g*4 + o];
        #pragma unroll
        for (int in = 0; in < 4; in++) {
            float s1r = w1r[g*16+in*4+0] + w1r[g*16+in*4+1] + w1r[g*16+in*4+2] + w1r[g*16+in*4+3];
            float yr  = vrp * s1r + b1r[g*4 + in];
            yr = yr > 0.f ? yr : 0.1f * yr;
            accr += w2r[g*16 + o*4 + in] * yr;
            float s1i = w1i[g*16+in*4+0] + w1i[g*16+in*4+1] + w1i[g*16+in*4+2] + w1i[g*16+in*4+3];
            float yi  = vip * s1i + b1i[g*4 + in];
            yi = yi > 0.f ? yi : 0.1f * yi;
            acci += w2i[g*16 + o*4 + in] * yi;
        }
        wr[p] = accr; wi[p] = acci;
    }
    // softmax over p (the +1/4 shift cancels)
    float mr = fmaxf(fmaxf(wr[0], wr[1]), fmaxf(wr[2], wr[3]));
    float mi = fmaxf(fmaxf(wi[0], wi[1]), fmaxf(wi[2], wi[3]));
    float er[4], ei[4], sumr = 0.f, sumi = 0.f;
    #pragma unroll
    for (int p = 0; p < 4; p++) {
        er[p] = expf(wr[p] - mr); sumr += er[p];
        ei[p] = expf(wi[p] - mi); sumi += ei[p];
    }
    float invr = 1.f / sumr, invi = 1.f / sumi;
    float outr = 0.f, outi = 0.f;
    #pragma unroll
    for (int p = 0; p < 4; p++) {
        float sp = er[p] * invr;
        float tp = ei[p] * invi;
        outr += vr[p] * sp - vi[p] * tp;
        outi += vr[p] * tp + vi[p] * sp;
    }
    g_LUTr[bc*256 + code] = outr;
    g_LUTi[bc*256 + code] = outi;
}

// ---------------- K4: permutation code per pixel ----------------
__global__ void k_code(const int* __restrict__ idx) {
    int t = blockIdx.x * blockDim.x + threadIdx.x;   // 0..65535  (= i*256 + j)
    int i0 = idx[t];
    int i1 = idx[t +     CHW1];
    int i2 = idx[t + 2 * CHW1];
    int i3 = idx[t + 3 * CHW1];
    g_codemap[t] = (unsigned char)(i0 | (i1 << 2) | (i2 << 4) | (i3 << 6));
}

// ---------------- warp-cooperative 256-pt Stockham inverse FFT (unnormalized) ----------------
// 32 lanes per FFT, data in warp-private shared ping-pong buffers. Result ends in bufA.
__device__ __forceinline__ void warp_fft256(float2* bufA, float2* bufB,
                                            const float2* __restrict__ twid, int lane) {
    float2* A = bufA;
    float2* B = bufB;
    #pragma unroll
    for (int s = 0; s < 8; s++) {
        int m = 1 << s;
        #pragma unroll
        for (int it = 0; it < 4; it++) {
            int t  = lane + it * 32;       // 0..127
            int k  = t & (m - 1);
            int jm = t - k;                // j*m
            float2 c0 = A[t];
            float2 c1 = A[t + 128];
            float2 tw = twid[jm];          // e^{+2pi i jm/256}
            float dr = c0.x - c1.x, di = c0.y - c1.y;
            B[2*jm + k]     = make_float2(c0.x + c1.x, c0.y + c1.y);
            B[2*jm + k + m] = make_float2(tw.x*dr - tw.y*di, tw.x*di + tw.y*dr);
        }
        float2* tp = A; A = B; B = tp;
        __syncwarp();
    }
}

#define WSTRIDE 264   // padded per-buffer stride (float2 elems) to dodge bank conflicts

// ---------------- K5: row-pass IFFT; writes transposed intermediate ----------------
__global__ void __launch_bounds__(256) k_rowfft() {
    __shared__ float2 sLUT[256];
    __shared__ float2 twid[128];
    __shared__ float2 buf[8 * 2 * WSTRIDE];
    int blk = blockIdx.x;           // 64*32
    int bc  = blk >> 5;
    int rg  = blk & 31;             // row group (8 rows)
    int tid = threadIdx.x, w = tid >> 5, lane = tid & 31;

    sLUT[tid] = make_float2(g_LUTr[bc*256 + tid], g_LUTi[bc*256 + tid]);
    if (tid < 128) {
        float sn, cn; sincosf(TWOPI * (float)tid / 256.0f, &sn, &cn);
        twid[tid] = make_float2(cn, sn);
    }
    __syncthreads();

    float2* A = buf + w * 2 * WSTRIDE;
    float2* B = A + WSTRIDE;
    int i = rg * 8 + w;
    const unsigned char* crow = g_codemap + i * WS;
    for (int j = lane; j < 256; j += 32) A[j] = sLUT[crow[j]];
    __syncwarp();
    warp_fft256(A, B, twid, lane);
    __syncthreads();

    // transposed write: g_tmp[bc][n][i]
    size_t base = (size_t)bc * 65536 + (size_t)rg * 8;
    #pragma unroll
    for (int it = 0; it < 8; it++) {
        int lin = it * 256 + tid;          // 0..2047
        int n   = lin >> 3;
        int il  = lin & 7;
        g_tmp[base + (size_t)n * 256 + il] = buf[il * 2 * WSTRIDE + n];
    }
}

// ---------------- K6: col-pass IFFT + |.|/65536 + 2x2 avg-pool(x) + store ----------------
__global__ void __launch_bounds__(256) k_colfft(const float* __restrict__ x,
                                                float* __restrict__ out) {
    __shared__ float2 twid[128];
    __shared__ float2 buf[8 * 2 * WSTRIDE];
    __shared__ float  sabs[8 * WSTRIDE];
    int blk = blockIdx.x;           // 64*32
    int bc  = blk >> 5;
    int cg  = blk & 31;             // column group (8 cols)
    int tid = threadIdx.x, w = tid >> 5, lane = tid & 31;

    if (tid < 128) {
        float sn, cn; sincosf(TWOPI * (float)tid / 256.0f, &sn, &cn);
        twid[tid] = make_float2(cn, sn);
    }
    __syncthreads();

    float2* A = buf + w * 2 * WSTRIDE;
    float2* B = A + WSTRIDE;
    int n = cg * 8 + w;
    const float2* src = g_tmp + (size_t)bc * 65536 + (size_t)n * 256;
    for (int i = lane; i < 256; i += 32) A[i] = src[i];
    __syncwarp();
    warp_fft256(A, B, twid, lane);
    for (int m = lane; m < 256; m += 32) {
        float2 z = A[m];
        sabs[w * WSTRIDE + m] = sqrtf(z.x*z.x + z.y*z.y) * (1.0f / 65536.0f);
    }
    __syncthreads();

    const float* xbc = x   + (size_t)bc * HH * WWID;
    float*       obc = out + (size_t)bc * HS * WS;
    #pragma unroll
    for (int it = 0; it < 8; it++) {
        int lin = it * 256 + tid;
        int m   = lin >> 3;
        int nl  = lin & 7;
        int nn  = cg * 8 + nl;
        const float2* xr0 = (const float2*)(xbc + (size_t)(2*m)     * WWID + 2*nn);
        const float2* xr1 = (const float2*)(xbc + (size_t)(2*m + 1) * WWID + 2*nn);
        float2 a = xr0[0], b2 = xr1[0];
        float d = 0.25f * (a.x + a.y + b2.x + b2.y);
        obc[(size_t)m * WS + nn] = sabs[nl * WSTRIDE + m] + d;
    }
}

// ---------------- launcher ----------------
extern "C" void kernel_launch(void* const* d_in, const int* in_sizes, int n_in,
                              void* d_out, int out_size) {
    // robust assignment by size (dict order preserved within equal-size groups)
    const float* x = nullptr; const int* idx = nullptr;
    const float* wmat[4] = {nullptr,nullptr,nullptr,nullptr};   // w1r,w2r,w1i,w2i (512 elems each)
    const float* bvec[4] = {nullptr,nullptr,nullptr,nullptr};   // b1r,b2r,b1i,b2i (128 elems each)
    int nw = 0, nb = 0;
    for (int i = 0; i < n_in; i++) {
        int sz = in_sizes[i];
        if      (sz == BATCH*CCH*HH*WWID) x   = (const float*)d_in[i];
        else if (sz == 4*CCH*HS*WS)       idx = (const int*)d_in[i];
        else if (sz == CCH*16)            { if (nw < 4) wmat[nw++] = (const float*)d_in[i]; }
        else if (sz == CCH*4)             { if (nb < 4) bvec[nb++] = (const float*)d_in[i]; }
    }
    const float *w1r = wmat[0], *w2r = wmat[1], *w1i = wmat[2], *w2i = wmat[3];
    const float *b1r = bvec[0], *b2r = bvec[1], *b1i = bvec[2], *b2i = bvec[3];
    float* out = (float*)d_out;

    k_colsum<<<dim3(64, BATCH), 512>>>(x);
    k_f4<<<BATCH, 512>>>();
    k_lut<<<NBC, 256>>>(w1r, b1r, w2r, b2r, w1i, b1i, w2i, b2i);
    k_code<<<256, 256>>>(idx);
    k_rowfft<<<NBC * 32, 256>>>();
    k_colfft<<<NBC * 32, 256>>>(x, out);
}